// round 14
// baseline (speedup 1.0000x reference)
#include <cuda_runtime.h>
#include <math.h>

// RoI Align pyramid (FPN) — per-warp cp.async pipeline, no block barriers.
//   d_in[0] metadata [1,3] f32, d_in[1] boxes [1,1024,4] f32
//   d_in[2..5] p2..p5: [1,H,H,256] f32, H = 256,128,64,32
// Output: [1,1024,7,7,256] f32
//
// One block per box, 64 threads = 2 warps. Warp w handles samples
// s = w, w+2, ... through a private 2-deep smem ring (4KB/stage).
// Lane l stages chunks l and l+32 of every corner with cp.async and
// consumes exactly the bytes it staged -> wait_group is sufficient
// ordering; no block/warp barriers in the pipeline.
// DEPTH=2 shrinks the ring to 16KB/block -> 14 CTAs/SM = 28 warps/SM
// (vs 18 at DEPTH=3): more independent request streams at the same
// total in-flight bytes. Streaming output stores (__stcs).

#define EXTENT 7
#define NSAMP  49
#define NBOX   1024
#define CH4    64u   // 256 channels / 4
#define DEPTH  2

__device__ __forceinline__ void cp_async16(void* smem_dst, const void* gsrc) {
    unsigned saddr = (unsigned)__cvta_generic_to_shared(smem_dst);
    asm volatile("cp.async.cg.shared.global [%0], [%1], 16;"
                 :: "r"(saddr), "l"(gsrc));
}
__device__ __forceinline__ void cp_async_commit() {
    asm volatile("cp.async.commit_group;");
}
__device__ __forceinline__ void cp_async_wait_upto1() {
    asm volatile("cp.async.wait_group 1;");   // DEPTH-1
}

__global__ __launch_bounds__(64, 14)
void roi_align_pyramid_kernel(const float* __restrict__ metadata,
                              const float* __restrict__ boxes,
                              const float* __restrict__ p2,
                              const float* __restrict__ p3,
                              const float* __restrict__ p4,
                              const float* __restrict__ p5,
                              float* __restrict__ out)
{
    // [warp][stage][corner][chunk]  = 2*2*4*64*16B = 16KB
    __shared__ float4 buf[2][DEPTH][4][CH4];

    const int box = blockIdx.x;

    const float rows = metadata[0];
    const float cols = metadata[1];

    const float x1 = boxes[box * 4 + 0];
    const float y1 = boxes[box * 4 + 1];
    const float x2 = boxes[box * 4 + 2];
    const float y2 = boxes[box * 4 + 3];

    const float h = y2 - y1;
    const float w = x2 - x1;

    // roi_level = clip(4 + round(log2(sqrt(h*w)/sqrt(rows*cols))), 2, 5)
    float rl = logf(sqrtf(h * w) / sqrtf(rows * cols)) * (1.0f / logf(2.0f));
    rl = fminf(5.0f, fmaxf(2.0f, 4.0f + rintf(rl)));
    const int lvl = (int)rl;  // 2..5

    const float* feat;
    int H;
    switch (lvl) {
        case 2: feat = p2; H = 256; break;
        case 3: feat = p3; H = 128; break;
        case 4: feat = p4; H = 64;  break;
        default: feat = p5; H = 32; break;
    }
    const int W = H;

    const float inv_r = 1.0f / (rows - 1.0f);
    const float inv_c = 1.0f / (cols - 1.0f);
    const float ny1 = y1 * inv_r;
    const float ny2 = y2 * inv_r;
    const float nx1 = x1 * inv_c;
    const float nx2 = x2 * inv_c;
    const float dny = ny2 - ny1;
    const float dnx = nx2 - nx1;
    const float Hm1 = (float)(H - 1);
    const float Wm1 = (float)(W - 1);
    const unsigned rowstep = (unsigned)W * CH4;  // float4 units

    const unsigned t  = threadIdx.x;
    const unsigned wp = t >> 5;   // warp 0..1
    const unsigned l  = t & 31u;  // lane

    const float4* __restrict__ f4 = (const float4*)feat;
    float4* __restrict__ o4 = (float4*)out + (unsigned)box * (NSAMP * CH4);

    // warp wp owns samples s = wp + 2*i
    const int nsw = (wp == 0) ? 25 : 24;

    auto sample_coords = [&](int s, float& ys, float& xs) {
        const int gy = s / EXTENT;
        const int gx = s - gy * EXTENT;
        const float gyf = (float)gy * (1.0f / (float)(EXTENT - 1));
        const float gxf = (float)gx * (1.0f / (float)(EXTENT - 1));
        ys = (ny1 + dny * gyf) * Hm1;
        xs = (nx1 + dnx * gxf) * Wm1;
    };

    // stage loads for owned-sample index i (always commits, maybe empty)
    auto issue = [&](int i) {
        if (i < nsw) {
            const int s = (int)wp + 2 * i;
            float ys, xs;
            sample_coords(s, ys, xs);
            const float y0f = fminf(fmaxf(floorf(ys), 0.0f), (float)(H - 2));
            const float x0f = fminf(fmaxf(floorf(xs), 0.0f), (float)(W - 2));
            const unsigned base = ((unsigned)((int)y0f * W + (int)x0f)) * CH4;
            const int st = i % DEPTH;
            const unsigned c0 = base + l;
            const unsigned c1 = base + CH4 + l;
            const unsigned c2 = base + rowstep + l;
            const unsigned c3 = base + rowstep + CH4 + l;
            cp_async16(&buf[wp][st][0][l],       &f4[c0]);
            cp_async16(&buf[wp][st][0][l + 32],  &f4[c0 + 32]);
            cp_async16(&buf[wp][st][1][l],       &f4[c1]);
            cp_async16(&buf[wp][st][1][l + 32],  &f4[c1 + 32]);
            cp_async16(&buf[wp][st][2][l],       &f4[c2]);
            cp_async16(&buf[wp][st][2][l + 32],  &f4[c2 + 32]);
            cp_async16(&buf[wp][st][3][l],       &f4[c3]);
            cp_async16(&buf[wp][st][3][l + 32],  &f4[c3 + 32]);
        }
        cp_async_commit();
    };

    issue(0);
    issue(1);

    for (int i = 0; i < nsw; i++) {
        const int s  = (int)wp + 2 * i;
        const int st = i % DEPTH;

        float ys, xs;
        sample_coords(s, ys, xs);
        const float y0f = fminf(fmaxf(floorf(ys), 0.0f), (float)(H - 2));
        const float x0f = fminf(fmaxf(floorf(xs), 0.0f), (float)(W - 2));
        const float wy = ys - y0f;
        const float wx = xs - x0f;
        const float w00 = (1.0f - wy) * (1.0f - wx);
        const float w01 = (1.0f - wy) * wx;
        const float w10 = wy * (1.0f - wx);
        const float w11 = wy * wx;

        cp_async_wait_upto1();   // stage i landed (this lane's own loads)

        const float4 a00 = buf[wp][st][0][l];
        const float4 a01 = buf[wp][st][1][l];
        const float4 a10 = buf[wp][st][2][l];
        const float4 a11 = buf[wp][st][3][l];
        float4 ra;
        ra.x = a00.x * w00 + a01.x * w01 + a10.x * w10 + a11.x * w11;
        ra.y = a00.y * w00 + a01.y * w01 + a10.y * w10 + a11.y * w11;
        ra.z = a00.z * w00 + a01.z * w01 + a10.z * w10 + a11.z * w11;
        ra.w = a00.w * w00 + a01.w * w01 + a10.w * w10 + a11.w * w11;
        __stcs(&o4[(unsigned)s * CH4 + l], ra);

        const float4 b00 = buf[wp][st][0][l + 32];
        const float4 b01 = buf[wp][st][1][l + 32];
        const float4 b10 = buf[wp][st][2][l + 32];
        const float4 b11 = buf[wp][st][3][l + 32];
        float4 rb;
        rb.x = b00.x * w00 + b01.x * w01 + b10.x * w10 + b11.x * w11;
        rb.y = b00.y * w00 + b01.y * w01 + b10.y * w10 + b11.y * w11;
        rb.z = b00.z * w00 + b01.z * w01 + b10.z * w10 + b11.z * w11;
        rb.w = b00.w * w00 + b01.w * w01 + b10.w * w10 + b11.w * w11;
        __stcs(&o4[(unsigned)s * CH4 + l + 32], rb);

        issue(i + DEPTH);        // refill the slot just drained
    }
}

extern "C" void kernel_launch(void* const* d_in, const int* in_sizes, int n_in,
                              void* d_out, int out_size)
{
    const float* metadata = (const float*)d_in[0];
    const float* boxes    = (const float*)d_in[1];
    const float* p2       = (const float*)d_in[2];
    const float* p3       = (const float*)d_in[3];
    const float* p4       = (const float*)d_in[4];
    const float* p5       = (const float*)d_in[5];
    float* out = (float*)d_out;

    roi_align_pyramid_kernel<<<NBOX, 64>>>(metadata, boxes, p2, p3, p4, p5, out);
}

// round 15
// speedup vs baseline: 1.3503x; 1.3503x over previous
#include <cuda_runtime.h>
#include <math.h>

// RoI Align pyramid (FPN) — per-warp cp.async.bulk (UBLKCP) pipeline.
//   d_in[0] metadata [1,3] f32, d_in[1] boxes [1,1024,4] f32
//   d_in[2..5] p2..p5: [1,H,H,256] f32, H = 256,128,64,32
// Output: [1,1024,7,7,256] f32
//
// One block per box, 64 threads = 2 warps. Warp w owns samples
// s = w, w+2, ... through a private 3-deep smem ring (4KB/stage =
// 4 corners x 1KB). Each corner row (256 ch x f32) is 1KB contiguous
// and 1KB aligned, so ONE cp.async.bulk per corner (issued by lane 0)
// replaces 8 LDGSTS warp-ops -> ~20x less LSU issue cost, which the
// R12 cycle audit showed to be the binding constraint (~11.8us of
// LDGSTS issue per SM). Completion via per-(warp,slot) mbarrier with
// expect_tx = 4KB; parity phase = (i/DEPTH)&1. No block barriers.

#define EXTENT 7
#define NSAMP  49
#define NBOX   1024
#define CH4    64u   // 256 channels / 4
#define DEPTH  3

__device__ __forceinline__ unsigned smem_u32(const void* p) {
    return (unsigned)__cvta_generic_to_shared(p);
}

__device__ __forceinline__ void mbar_init(unsigned mb, unsigned count) {
    asm volatile("mbarrier.init.shared.b64 [%0], %1;" :: "r"(mb), "r"(count) : "memory");
}
__device__ __forceinline__ void mbar_expect_tx(unsigned mb, unsigned bytes) {
    asm volatile("mbarrier.arrive.expect_tx.shared.b64 _, [%0], %1;"
                 :: "r"(mb), "r"(bytes) : "memory");
}
__device__ __forceinline__ void mbar_wait_parity(unsigned mb, unsigned parity) {
    asm volatile(
        "{\n\t"
        ".reg .pred P;\n\t"
        "WAIT_%=:\n\t"
        "mbarrier.try_wait.parity.acquire.cta.shared::cta.b64 P, [%0], %1, 0x989680;\n\t"
        "@P bra.uni DONE_%=;\n\t"
        "bra.uni WAIT_%=;\n\t"
        "DONE_%=:\n\t"
        "}"
        :: "r"(mb), "r"(parity) : "memory");
}
__device__ __forceinline__ void bulk_g2s(unsigned sdst, const void* gsrc,
                                         unsigned bytes, unsigned mb) {
    asm volatile(
        "cp.async.bulk.shared::cta.global.mbarrier::complete_tx::bytes [%0], [%1], %2, [%3];"
        :: "r"(sdst), "l"(gsrc), "r"(bytes), "r"(mb) : "memory");
}

__global__ __launch_bounds__(64, 9)
void roi_align_pyramid_kernel(const float* __restrict__ metadata,
                              const float* __restrict__ boxes,
                              const float* __restrict__ p2,
                              const float* __restrict__ p3,
                              const float* __restrict__ p4,
                              const float* __restrict__ p5,
                              float* __restrict__ out)
{
    // [warp][stage][corner][chunk] = 2*3*4*64*16B = 24KB
    __shared__ __align__(128) float4 buf[2][DEPTH][4][CH4];
    __shared__ unsigned long long mbar[2][DEPTH];

    const int box = blockIdx.x;

    const float rows = metadata[0];
    const float cols = metadata[1];

    const float x1 = boxes[box * 4 + 0];
    const float y1 = boxes[box * 4 + 1];
    const float x2 = boxes[box * 4 + 2];
    const float y2 = boxes[box * 4 + 3];

    const float h = y2 - y1;
    const float w = x2 - x1;

    // roi_level = clip(4 + round(log2(sqrt(h*w)/sqrt(rows*cols))), 2, 5)
    float rl = logf(sqrtf(h * w) / sqrtf(rows * cols)) * (1.0f / logf(2.0f));
    rl = fminf(5.0f, fmaxf(2.0f, 4.0f + rintf(rl)));
    const int lvl = (int)rl;  // 2..5

    const float* feat;
    int H;
    switch (lvl) {
        case 2: feat = p2; H = 256; break;
        case 3: feat = p3; H = 128; break;
        case 4: feat = p4; H = 64;  break;
        default: feat = p5; H = 32; break;
    }
    const int W = H;

    const float inv_r = 1.0f / (rows - 1.0f);
    const float inv_c = 1.0f / (cols - 1.0f);
    const float ny1 = y1 * inv_r;
    const float ny2 = y2 * inv_r;
    const float nx1 = x1 * inv_c;
    const float nx2 = x2 * inv_c;
    const float dny = ny2 - ny1;
    const float dnx = nx2 - nx1;
    const float Hm1 = (float)(H - 1);
    const float Wm1 = (float)(W - 1);
    const unsigned rowstep = (unsigned)W * CH4;  // float4 units

    const unsigned t  = threadIdx.x;
    const unsigned wp = t >> 5;   // warp 0..1
    const unsigned l  = t & 31u;  // lane

    const float4* __restrict__ f4 = (const float4*)feat;
    float4* __restrict__ o4 = (float4*)out + (unsigned)box * (NSAMP * CH4);

    // per-warp mbarrier init (warp-scoped, no block barrier needed)
    if (l == 0) {
        #pragma unroll
        for (int st = 0; st < DEPTH; st++)
            mbar_init(smem_u32(&mbar[wp][st]), 1);
    }
    __syncwarp();

    // warp wp owns samples s = wp + 2*i
    const int nsw = (wp == 0) ? 25 : 24;

    auto sample_coords = [&](int s, float& ys, float& xs) {
        const int gy = s / EXTENT;
        const int gx = s - gy * EXTENT;
        const float gyf = (float)gy * (1.0f / (float)(EXTENT - 1));
        const float gxf = (float)gx * (1.0f / (float)(EXTENT - 1));
        ys = (ny1 + dny * gyf) * Hm1;
        xs = (nx1 + dnx * gxf) * Wm1;
    };

    // lane 0 stages 4x 1KB bulk copies for owned-sample index i
    auto issue = [&](int i) {
        if (i < nsw && l == 0) {
            const int s = (int)wp + 2 * i;
            float ys, xs;
            sample_coords(s, ys, xs);
            const float y0f = fminf(fmaxf(floorf(ys), 0.0f), (float)(H - 2));
            const float x0f = fminf(fmaxf(floorf(xs), 0.0f), (float)(W - 2));
            const unsigned base = ((unsigned)((int)y0f * W + (int)x0f)) * CH4;
            const int st = i % DEPTH;
            const unsigned mb = smem_u32(&mbar[wp][st]);
            mbar_expect_tx(mb, 4096);
            bulk_g2s(smem_u32(&buf[wp][st][0][0]), &f4[base],                 1024, mb);
            bulk_g2s(smem_u32(&buf[wp][st][1][0]), &f4[base + CH4],           1024, mb);
            bulk_g2s(smem_u32(&buf[wp][st][2][0]), &f4[base + rowstep],       1024, mb);
            bulk_g2s(smem_u32(&buf[wp][st][3][0]), &f4[base + rowstep + CH4], 1024, mb);
        }
    };

    issue(0);
    issue(1);
    issue(2);

    for (int i = 0; i < nsw; i++) {
        const int s  = (int)wp + 2 * i;
        const int st = i % DEPTH;
        const unsigned parity = ((unsigned)(i / DEPTH)) & 1u;

        float ys, xs;
        sample_coords(s, ys, xs);
        const float y0f = fminf(fmaxf(floorf(ys), 0.0f), (float)(H - 2));
        const float x0f = fminf(fmaxf(floorf(xs), 0.0f), (float)(W - 2));
        const float wy = ys - y0f;
        const float wx = xs - x0f;
        const float w00 = (1.0f - wy) * (1.0f - wx);
        const float w01 = (1.0f - wy) * wx;
        const float w10 = wy * (1.0f - wx);
        const float w11 = wy * wx;

        mbar_wait_parity(smem_u32(&mbar[wp][st]), parity);

        const float4 a00 = buf[wp][st][0][l];
        const float4 a01 = buf[wp][st][1][l];
        const float4 a10 = buf[wp][st][2][l];
        const float4 a11 = buf[wp][st][3][l];
        float4 ra;
        ra.x = a00.x * w00 + a01.x * w01 + a10.x * w10 + a11.x * w11;
        ra.y = a00.y * w00 + a01.y * w01 + a10.y * w10 + a11.y * w11;
        ra.z = a00.z * w00 + a01.z * w01 + a10.z * w10 + a11.z * w11;
        ra.w = a00.w * w00 + a01.w * w01 + a10.w * w10 + a11.w * w11;
        __stcs(&o4[(unsigned)s * CH4 + l], ra);

        const float4 b00 = buf[wp][st][0][l + 32];
        const float4 b01 = buf[wp][st][1][l + 32];
        const float4 b10 = buf[wp][st][2][l + 32];
        const float4 b11 = buf[wp][st][3][l + 32];
        float4 rb;
        rb.x = b00.x * w00 + b01.x * w01 + b10.x * w10 + b11.x * w11;
        rb.y = b00.y * w00 + b01.y * w01 + b10.y * w10 + b11.y * w11;
        rb.z = b00.z * w00 + b01.z * w01 + b10.z * w10 + b11.z * w11;
        rb.w = b00.w * w00 + b01.w * w01 + b10.w * w10 + b11.w * w11;
        __stcs(&o4[(unsigned)s * CH4 + l + 32], rb);

        issue(i + DEPTH);        // refill the slot just drained
    }
}

extern "C" void kernel_launch(void* const* d_in, const int* in_sizes, int n_in,
                              void* d_out, int out_size)
{
    const float* metadata = (const float*)d_in[0];
    const float* boxes    = (const float*)d_in[1];
    const float* p2       = (const float*)d_in[2];
    const float* p3       = (const float*)d_in[3];
    const float* p4       = (const float*)d_in[4];
    const float* p5       = (const float*)d_in[5];
    float* out = (float*)d_out;

    roi_align_pyramid_kernel<<<NBOX, 64>>>(metadata, boxes, p2, p3, p4, p5, out);
}